// round 5
// baseline (speedup 1.0000x reference)
#include <cuda_runtime.h>

#define TOK   4096
#define DH    16384
#define DM    1024
#define KSEL  64
#define CMAX  192          // max near-boundary candidates per row
#define RWIN  4e-4f        // refinement window (abs), >> fp32 dot error

// ---- scratch (device globals; no runtime allocation) ----
__device__ float g_z[(long)TOK * DH];       // 256 MB post-ReLU pre-activations
__device__ int   g_idx[TOK * KSEL];
__device__ float g_val[TOK * KSEL];
__device__ int   g_cnt[TOK];

// ============================================================
// Encode: z = relu(x @ W_enc + b_enc), SIMT fp32 tiled GEMM
// M=4096, N=16384, K=1024. 128x128x16 tile, 256 thr, 8x8/thread
// Sequential ascending-k fp32 FMA accumulation per output.
// ============================================================
#define BM 128
#define BN 128
#define BK 16

__global__ __launch_bounds__(256) void encode_kernel(
    const float* __restrict__ A,     // x [TOK, DM]
    const float* __restrict__ B,     // W_enc [DM, DH]
    const float* __restrict__ bias)  // b_enc [DH]
{
    __shared__ float As[BK][BM];
    __shared__ float Bs[BK][BN];

    const int tid = threadIdx.x;
    const int tx = tid & 15;
    const int ty = tid >> 4;
    const int m0 = blockIdx.y * BM;
    const int n0 = blockIdx.x * BN;

    const int arow = tid >> 2;
    const int acol = (tid & 3) << 2;
    const int brow = tid >> 5;
    const int bcol = (tid & 31) << 2;

    const float* Ab = A + (long)m0 * DM;
    const float* Bb = B + n0;

    float acc[8][8];
#pragma unroll
    for (int i = 0; i < 8; i++)
#pragma unroll
        for (int j = 0; j < 8; j++) acc[i][j] = 0.f;

    float4 pa0 = *(const float4*)(Ab + (long)arow        * DM + acol);
    float4 pa1 = *(const float4*)(Ab + (long)(arow + 64) * DM + acol);
    float4 pb0 = *(const float4*)(Bb + (long)brow        * DH + bcol);
    float4 pb1 = *(const float4*)(Bb + (long)(brow + 8)  * DH + bcol);

    As[acol+0][arow]    = pa0.x; As[acol+1][arow]    = pa0.y;
    As[acol+2][arow]    = pa0.z; As[acol+3][arow]    = pa0.w;
    As[acol+0][arow+64] = pa1.x; As[acol+1][arow+64] = pa1.y;
    As[acol+2][arow+64] = pa1.z; As[acol+3][arow+64] = pa1.w;
    *(float4*)&Bs[brow][bcol]     = pb0;
    *(float4*)&Bs[brow + 8][bcol] = pb1;
    __syncthreads();

    for (int k0 = 0; k0 < DM; k0 += BK) {
        const bool more = (k0 + BK) < DM;
        if (more) {
            pa0 = *(const float4*)(Ab + (long)arow        * DM + (k0 + BK) + acol);
            pa1 = *(const float4*)(Ab + (long)(arow + 64) * DM + (k0 + BK) + acol);
            pb0 = *(const float4*)(Bb + (long)(k0 + BK + brow)     * DH + bcol);
            pb1 = *(const float4*)(Bb + (long)(k0 + BK + brow + 8) * DH + bcol);
        }
#pragma unroll
        for (int kk = 0; kk < BK; kk++) {
            float a[8], b[8];
            *(float4*)&a[0] = *(const float4*)&As[kk][ty * 4];
            *(float4*)&a[4] = *(const float4*)&As[kk][64 + ty * 4];
            *(float4*)&b[0] = *(const float4*)&Bs[kk][tx * 4];
            *(float4*)&b[4] = *(const float4*)&Bs[kk][64 + tx * 4];
#pragma unroll
            for (int i = 0; i < 8; i++)
#pragma unroll
                for (int j = 0; j < 8; j++)
                    acc[i][j] = fmaf(a[i], b[j], acc[i][j]);
        }
        __syncthreads();
        if (more) {
            As[acol+0][arow]    = pa0.x; As[acol+1][arow]    = pa0.y;
            As[acol+2][arow]    = pa0.z; As[acol+3][arow]    = pa0.w;
            As[acol+0][arow+64] = pa1.x; As[acol+1][arow+64] = pa1.y;
            As[acol+2][arow+64] = pa1.z; As[acol+3][arow+64] = pa1.w;
            *(float4*)&Bs[brow][bcol]     = pb0;
            *(float4*)&Bs[brow + 8][bcol] = pb1;
            __syncthreads();
        }
    }

    float bl[8];
#pragma unroll
    for (int j = 0; j < 8; j++) {
        int n = n0 + ((j < 4) ? (tx * 4 + j) : (64 + tx * 4 + (j - 4)));
        bl[j] = bias[n];
    }
#pragma unroll
    for (int i = 0; i < 8; i++) {
        int m = m0 + ((i < 4) ? (ty * 4 + i) : (64 + ty * 4 + (i - 4)));
        float* crow = g_z + (long)m * DH + n0;
        float4 o0, o1;
        o0.x = fmaxf(acc[i][0] + bl[0], 0.f);
        o0.y = fmaxf(acc[i][1] + bl[1], 0.f);
        o0.z = fmaxf(acc[i][2] + bl[2], 0.f);
        o0.w = fmaxf(acc[i][3] + bl[3], 0.f);
        o1.x = fmaxf(acc[i][4] + bl[4], 0.f);
        o1.y = fmaxf(acc[i][5] + bl[5], 0.f);
        o1.z = fmaxf(acc[i][6] + bl[6], 0.f);
        o1.w = fmaxf(acc[i][7] + bl[7], 0.f);
        *(float4*)(crow + tx * 4)      = o0;
        *(float4*)(crow + 64 + tx * 4) = o1;
    }
}

// ============================================================
// TopK with exact (fp64) boundary refinement.
// Binary-search threshold t on uint bit space (z >= 0).
// Elements > t+W are certainly-in; elements in [t-W, t+W] get
// exact fp64 recompute and are ranked exactly (index tiebreak).
// ============================================================
__global__ __launch_bounds__(256) void topk_kernel(
    const float* __restrict__ X,      // x [TOK, DM]
    const float* __restrict__ Wenc,   // [DM, DH]
    const float* __restrict__ benc)   // [DH]
{
    extern __shared__ unsigned sm[];   // DH values (64 KB)
    __shared__ int    s_red;
    __shared__ int    s_scan[256];
    __shared__ int    s_cidx[CMAX];
    __shared__ double s_cval[CMAX];
    __shared__ double s_wred[8];
    __shared__ int    s_cA, s_cC;

    const int row = blockIdx.x;
    const int tid = threadIdx.x;
    const unsigned* z = (const unsigned*)(g_z + (long)row * DH);

    // stage row in smem
    const uint4* z4 = (const uint4*)z;
    uint4* s4 = (uint4*)sm;
    for (int i = tid; i < DH / 4; i += 256) s4[i] = z4[i];
    __syncthreads();

    // largest t with count(v >= t) >= KSEL
    unsigned lo = 0u, hi = 0x7F800000u;
    while (lo < hi) {
        unsigned mid = lo + ((hi - lo + 1) >> 1);
        if (tid == 0) s_red = 0;
        __syncthreads();
        int c = 0;
#pragma unroll 8
        for (int i = 0; i < DH / 256; i++)
            c += (sm[i * 256 + tid] >= mid) ? 1 : 0;
#pragma unroll
        for (int o = 16; o; o >>= 1) c += __shfl_xor_sync(0xFFFFFFFFu, c, o);
        if ((tid & 31) == 0) atomicAdd(&s_red, c);
        __syncthreads();
        int cnt = s_red;
        if (cnt >= KSEL) lo = mid; else hi = mid - 1;
        __syncthreads();
    }
    const unsigned t = lo;
    const float tf = __uint_as_float(t);
    const int base = tid * (DH / 256);

    bool done = false;

    if (tf > 2.0f * RWIN) {
        const unsigned hib = __float_as_uint(tf + RWIN);
        const unsigned lob = __float_as_uint(tf - RWIN);

        // --- candidate count + gather (v in [lob, hib]) ---
        int nc = 0;
#pragma unroll 8
        for (int i = 0; i < DH / 256; i++) {
            unsigned v = sm[base + i];
            nc += (v >= lob && v <= hib) ? 1 : 0;
        }
        s_scan[tid] = nc;
        __syncthreads();
        for (int off = 1; off < 256; off <<= 1) {
            int v = (tid >= off) ? s_scan[tid - off] : 0;
            __syncthreads();
            s_scan[tid] += v;
            __syncthreads();
        }
        const int cC = s_scan[255];
        if (cC <= CMAX) {
            int cw = s_scan[tid] - nc;
            for (int i = 0; i < DH / 256; i++) {
                unsigned v = sm[base + i];
                if (v >= lob && v <= hib) s_cidx[cw++] = base + i;
            }
            __syncthreads();

            // --- pass A: certainly-in (v > hib), ascending index ---
            int ng = 0;
#pragma unroll 8
            for (int i = 0; i < DH / 256; i++) ng += (sm[base + i] > hib) ? 1 : 0;
            s_scan[tid] = ng;
            __syncthreads();
            for (int off = 1; off < 256; off <<= 1) {
                int v = (tid >= off) ? s_scan[tid - off] : 0;
                __syncthreads();
                s_scan[tid] += v;
                __syncthreads();
            }
            const int cA = s_scan[255];   // <= count(v>t) < KSEL
            int w = s_scan[tid] - ng;
            for (int i = 0; i < DH / 256; i++) {
                unsigned v = sm[base + i];
                if (v > hib) {
                    g_idx[row * KSEL + w] = base + i;
                    g_val[row * KSEL + w] = __uint_as_float(v);
                    w++;
                }
            }
            __syncthreads();

            // --- exact fp64 recompute of candidates (block-cooperative) ---
            const float* xr = X + (long)row * DM;
            for (int c = 0; c < cC; c++) {
                const int fi = s_cidx[c];
                double part = 0.0;
                for (int k = tid; k < DM; k += 256)
                    part += (double)xr[k] * (double)Wenc[(long)k * DH + fi];
#pragma unroll
                for (int o = 16; o; o >>= 1)
                    part += __shfl_down_sync(0xFFFFFFFFu, part, o);
                if ((tid & 31) == 0) s_wred[tid >> 5] = part;
                __syncthreads();
                if (tid == 0) {
                    double s = 0.0;
#pragma unroll
                    for (int wd = 0; wd < 8; wd++) s += s_wred[wd];
                    s += (double)benc[fi];
                    s_cval[c] = s > 0.0 ? s : 0.0;
                }
                __syncthreads();
            }

            // --- rank candidates by exact value desc, index asc; keep top need ---
            const int need = KSEL - cA;
            for (int c = tid; c < cC; c += 256) {
                const double v = s_cval[c];
                const int fi = s_cidx[c];
                int rank = 0;
                for (int c2 = 0; c2 < cC; c2++) {
                    const double u = s_cval[c2];
                    if (u > v || (u == v && s_cidx[c2] < fi)) rank++;
                }
                if (rank < need) {
                    g_idx[row * KSEL + cA + rank] = fi;
                    g_val[row * KSEL + cA + rank] = __uint_as_float(sm[fi]);
                }
            }
            if (tid == 0) g_cnt[row] = KSEL;
            done = true;
        }
        __syncthreads();
    }

    if (!done) {
        // ---- legacy fp32 path (t near zero, or candidate overflow) ----
        int ng = 0;
#pragma unroll 8
        for (int i = 0; i < DH / 256; i++) ng += (sm[base + i] > t) ? 1 : 0;
        s_scan[tid] = ng;
        __syncthreads();
        for (int off = 1; off < 256; off <<= 1) {
            int v = (tid >= off) ? s_scan[tid - off] : 0;
            __syncthreads();
            s_scan[tid] += v;
            __syncthreads();
        }
        const int c_gt = s_scan[255];
        int w = s_scan[tid] - ng;
        for (int i = 0; i < DH / 256; i++) {
            unsigned v = sm[base + i];
            if (v > t) {
                g_idx[row * KSEL + w] = base + i;
                g_val[row * KSEL + w] = __uint_as_float(v);
                w++;
            }
        }

        int cnt_final = c_gt;
        if (t != 0u) {
            __syncthreads();
            int ne = 0;
#pragma unroll 8
            for (int i = 0; i < DH / 256; i++) ne += (sm[base + i] == t) ? 1 : 0;
            s_scan[tid] = ne;
            __syncthreads();
            for (int off = 1; off < 256; off <<= 1) {
                int v = (tid >= off) ? s_scan[tid - off] : 0;
                __syncthreads();
                s_scan[tid] += v;
                __syncthreads();
            }
            int pos = c_gt + s_scan[tid] - ne;
            for (int i = 0; i < DH / 256; i++) {
                if (sm[base + i] == t) {
                    if (pos < KSEL) {
                        g_idx[row * KSEL + pos] = base + i;
                        g_val[row * KSEL + pos] = __uint_as_float(t);
                    }
                    pos++;
                }
            }
            cnt_final = KSEL;
        }
        if (tid == 0) g_cnt[row] = cnt_final;
    }
}

// ============================================================
// Decode: y[row,:] = b_dec + sum_j val_j * W_dec[idx_j, :]
// ============================================================
__global__ __launch_bounds__(256) void decode_kernel(
    const float* __restrict__ Wd,    // [DH, DM]
    const float* __restrict__ bd,    // [DM]
    float* __restrict__ Y)           // [TOK, DM]
{
    __shared__ float s_val[KSEL];
    __shared__ int   s_idx[KSEL];
    const int row = blockIdx.x;
    const int tid = threadIdx.x;
    const int cnt = g_cnt[row];

    if (tid < KSEL) {
        s_idx[tid] = (tid < cnt) ? g_idx[row * KSEL + tid] : 0;
        s_val[tid] = (tid < cnt) ? g_val[row * KSEL + tid] : 0.f;
    }
    __syncthreads();

    float4 acc = ((const float4*)bd)[tid];
#pragma unroll 4
    for (int j = 0; j < cnt; j++) {
        const float v = s_val[j];
        const float4 wv = ((const float4*)(Wd + (long)s_idx[j] * DM))[tid];
        acc.x = fmaf(v, wv.x, acc.x);
        acc.y = fmaf(v, wv.y, acc.y);
        acc.z = fmaf(v, wv.z, acc.z);
        acc.w = fmaf(v, wv.w, acc.w);
    }
    ((float4*)Y)[(long)row * (DM / 4) + tid] = acc;
}

// ============================================================
extern "C" void kernel_launch(void* const* d_in, const int* in_sizes, int n_in,
                              void* d_out, int out_size)
{
    const float* x     = (const float*)d_in[0];
    const float* W_enc = (const float*)d_in[1];
    const float* b_enc = (const float*)d_in[2];
    const float* W_dec = (const float*)d_in[3];
    const float* b_dec = (const float*)d_in[4];
    float* y = (float*)d_out;

    dim3 ge(DH / BN, TOK / BM);   // (128, 32)
    encode_kernel<<<ge, 256>>>(x, W_enc, b_enc);

    cudaFuncSetAttribute(topk_kernel,
                         cudaFuncAttributeMaxDynamicSharedMemorySize, DH * 4);
    topk_kernel<<<TOK, 256, DH * 4>>>(x, W_enc, b_enc);

    decode_kernel<<<TOK, 256>>>(W_dec, b_dec, y);
}

// round 9
// speedup vs baseline: 3.8637x; 3.8637x over previous
#include <cuda_runtime.h>
#include <cuda_bf16.h>
#include <cstdint>

#define TOK   4096
#define DH    16384
#define DM    1024
#define KSEL  64
#define CMAX  192
#define RWIN  1.5e-2f

// ---- scratch (device globals; no runtime allocation) ----
__device__ float g_z[(long)TOK * DH];                        // 256 MB z~ (bf16-accurate)
__device__ __align__(16) __nv_bfloat16 g_Abf[(long)TOK * DM];
__device__ __align__(16) __nv_bfloat16 g_Bbf[(long)DH * DM]; // W_enc^T bf16
__device__ __align__(16) float         g_WT [(long)DH * DM]; // W_enc^T fp32 (exact recompute)
__device__ int   g_idx[TOK * KSEL];
__device__ float g_val[TOK * KSEL];
__device__ int   g_cnt[TOK];

// ============================================================
// helpers
// ============================================================
__device__ __forceinline__ uint32_t smem_u32(const void* p) {
    uint32_t a;
    asm("{ .reg .u64 t; cvta.to.shared.u64 t, %1; cvt.u32.u64 %0, t; }"
        : "=r"(a) : "l"(p));
    return a;
}
#define SWZ128(o) ((o) ^ (((o) >> 3) & 0x70))

#define CPASYNC16(dst, src) \
    asm volatile("cp.async.cg.shared.global [%0], [%1], 16;" \
                 :: "r"(dst), "l"(src) : "memory")
#define CP_COMMIT() asm volatile("cp.async.commit_group;" ::: "memory")

#define MMA16816(c, a, b0, b1) \
    asm volatile("mma.sync.aligned.m16n8k16.row.col.f32.bf16.bf16.f32 " \
        "{%0,%1,%2,%3}, {%4,%5,%6,%7}, {%8,%9}, {%0,%1,%2,%3};" \
        : "+f"((c)[0]), "+f"((c)[1]), "+f"((c)[2]), "+f"((c)[3]) \
        : "r"((a)[0]), "r"((a)[1]), "r"((a)[2]), "r"((a)[3]), "r"(b0), "r"(b1))

#define LDMATX4(r, ad) \
    asm volatile("ldmatrix.sync.aligned.m8n8.x4.shared.b16 {%0,%1,%2,%3}, [%4];" \
        : "=r"((r)[0]), "=r"((r)[1]), "=r"((r)[2]), "=r"((r)[3]) : "r"(ad))

// ---- double-float (exact-ish) dot product, warp-cooperative ----
__device__ __forceinline__ void two_sum(float a, float b, float& s, float& e) {
    s = a + b;
    float bv = s - a;
    e = (a - (s - bv)) + (b - bv);
}
__device__ __forceinline__ double df_dot_warp(const float* __restrict__ x,
                                              const float* __restrict__ w,
                                              int lane) {
    float hi = 0.f, lo = 0.f;
    for (int k = lane; k < DM; k += 32) {
        float xv = x[k], wv = w[k];
        float p  = xv * wv;
        float pe = fmaf(xv, wv, -p);
        float s, e;
        two_sum(hi, p, s, e);
        lo += e + pe;
        hi = s;
    }
#pragma unroll
    for (int off = 16; off; off >>= 1) {
        float h2 = __shfl_down_sync(0xFFFFFFFFu, hi, off);
        float l2 = __shfl_down_sync(0xFFFFFFFFu, lo, off);
        float s, e;
        two_sum(hi, h2, s, e);
        lo = lo + l2 + e;
        hi = s;
    }
    return (double)hi + (double)lo;     // valid on lane 0
}

// ============================================================
// Prepass 1: x -> bf16
// ============================================================
__global__ __launch_bounds__(256) void split_x_kernel(const float* __restrict__ x)
{
    long i = (long)blockIdx.x * 256 + threadIdx.x;      // float4 index
    float4 v = ((const float4*)x)[i];
    __nv_bfloat16 h[4];
    h[0] = __float2bfloat16(v.x); h[1] = __float2bfloat16(v.y);
    h[2] = __float2bfloat16(v.z); h[3] = __float2bfloat16(v.w);
    ((uint2*)g_Abf)[i] = *(uint2*)h;
}

// ============================================================
// Prepass 2: transpose W_enc [DM,DH] -> [DH,DM] fp32 + bf16
// ============================================================
__global__ __launch_bounds__(256) void split_w_kernel(const float* __restrict__ W)
{
    __shared__ float s[32][33];
    const int n0 = blockIdx.x * 32, k0 = blockIdx.y * 32;
    const int tx = threadIdx.x, ty = threadIdx.y;   // 32 x 8
#pragma unroll
    for (int i = 0; i < 4; i++)
        s[ty + 8 * i][tx] = W[(long)(k0 + ty + 8 * i) * DH + n0 + tx];
    __syncthreads();
#pragma unroll
    for (int i = 0; i < 4; i++) {
        const int n = n0 + ty + 8 * i, k = k0 + tx;
        const float f = s[tx][ty + 8 * i];
        g_WT [(long)n * DM + k] = f;
        g_Bbf[(long)n * DM + k] = __float2bfloat16(f);
    }
}

// ============================================================
// Encode GEMM: bf16 mma.sync (HMMA), 128x256 CTA, 64x64 warps,
// BK=64, SW128 K-major smem, 3-stage cp.async pipeline.
// ============================================================
#define BM 128
#define BN 256
#define BKG 64
#define ASTG 16384
#define STAGE 49152
#define NSTG 3
#define SMEM_DYN (NSTG * STAGE)

__global__ __launch_bounds__(256, 1) void encode_mma_kernel(const float* __restrict__ bias)
{
    extern __shared__ __align__(1024) char smem[];
    const uint32_t smb = smem_u32(smem);
    const int tid = threadIdx.x, lane = tid & 31, wid = tid >> 5;
    const int wm = wid >> 2, wn = wid & 3;          // warp grid 2 x 4
    const int m0 = blockIdx.y * BM, n0 = blockIdx.x * BN;

    // ---- cp.async assignments (A: 1024 chunks, B: 2048 chunks of 16B) ----
    int arow[4], bro[8];
    uint32_t asw[4], bsw[8];
    long asrc[4], bsrc[8];
#pragma unroll
    for (int i = 0; i < 4; i++) {
        int c = tid + 256 * i;
        arow[i] = c >> 3;
        int ch = c & 7;
        asw[i] = SWZ128((uint32_t)(arow[i] * 128 + ch * 16));
        asrc[i] = (long)(m0 + arow[i]) * DM + ch * 8;
    }
#pragma unroll
    for (int i = 0; i < 8; i++) {
        int c = tid + 256 * i;
        bro[i] = c >> 3;
        int ch = c & 7;
        bsw[i] = SWZ128((uint32_t)(bro[i] * 128 + ch * 16));
        bsrc[i] = (long)(n0 + bro[i]) * DM + ch * 8;
    }

    // ---- ldmatrix lane coordinates ----
    const int rowA = wm * 64 + (lane & 7) + ((lane >> 3) & 1) * 8;
    const int kbA  = ((lane >> 4) & 1) * 16;
    const int rowB = wn * 64 + (lane & 7) + ((lane >> 4) & 1) * 8;
    const int kbB  = ((lane >> 3) & 1) * 16;

    float acc[4][8][4];
#pragma unroll
    for (int m = 0; m < 4; m++)
#pragma unroll
        for (int n = 0; n < 8; n++)
#pragma unroll
            for (int r = 0; r < 4; r++) acc[m][n][r] = 0.f;

    auto issue = [&](int k0, int s) {
        const uint32_t As = smb + s * STAGE;
        const uint32_t Bs = As + ASTG;
#pragma unroll
        for (int i = 0; i < 4; i++)
            CPASYNC16(As + asw[i], (const char*)(g_Abf + asrc[i] + k0));
#pragma unroll
        for (int i = 0; i < 8; i++)
            CPASYNC16(Bs + bsw[i], (const char*)(g_Bbf + bsrc[i] + k0));
    };

    auto compute = [&](int s) {
        const uint32_t As = smb + s * STAGE;
        const uint32_t Bs = As + ASTG;
#pragma unroll
        for (int ks = 0; ks < 4; ks++) {
            uint32_t a[4][4], bq[4][4];
#pragma unroll
            for (int mt = 0; mt < 4; mt++) {
                uint32_t off = (uint32_t)((rowA + mt * 16) * 128 + ks * 32 + kbA);
                LDMATX4(a[mt], As + SWZ128(off));
            }
#pragma unroll
            for (int j = 0; j < 4; j++) {
                uint32_t off = (uint32_t)((rowB + j * 16) * 128 + ks * 32 + kbB);
                LDMATX4(bq[j], Bs + SWZ128(off));
            }
#pragma unroll
            for (int mt = 0; mt < 4; mt++)
#pragma unroll
                for (int j = 0; j < 4; j++) {
                    MMA16816(acc[mt][2 * j],     a[mt], bq[j][0], bq[j][1]);
                    MMA16816(acc[mt][2 * j + 1], a[mt], bq[j][2], bq[j][3]);
                }
        }
    };

    // ---- pipeline ----
    issue(0, 0);   CP_COMMIT();
    issue(64, 1);  CP_COMMIT();

    const int NIT = DM / BKG;   // 16
    for (int i = 0; i < NIT; i++) {
        if (i < NIT - 2) asm volatile("cp.async.wait_group 1;" ::: "memory");
        else             asm volatile("cp.async.wait_group 0;" ::: "memory");
        __syncthreads();
        compute(i % NSTG);
        if (i + 2 < NIT) {
            issue((i + 2) * BKG, (i + 2) % NSTG);
            CP_COMMIT();
        }
    }

    // ---- epilogue: bias + ReLU -> g_z ----
    const int r0  = m0 + wm * 64 + (lane >> 2);
    const int c0  = n0 + wn * 64 + (lane & 3) * 2;
#pragma unroll
    for (int nt = 0; nt < 8; nt++) {
        const int col = c0 + nt * 8;
        const float2 bv = *(const float2*)&bias[col];
#pragma unroll
        for (int mt = 0; mt < 4; mt++) {
            const int r = r0 + mt * 16;
            float2 o0, o1;
            o0.x = fmaxf(acc[mt][nt][0] + bv.x, 0.f);
            o0.y = fmaxf(acc[mt][nt][1] + bv.y, 0.f);
            o1.x = fmaxf(acc[mt][nt][2] + bv.x, 0.f);
            o1.y = fmaxf(acc[mt][nt][3] + bv.y, 0.f);
            *(float2*)&g_z[(long)r * DH + col]       = o0;
            *(float2*)&g_z[(long)(r + 8) * DH + col] = o1;
        }
    }
}

// ============================================================
// TopK: threshold on z~, wide window, double-float exact ranking
// of boundary candidates + exact recompute of all selected vals.
// ============================================================
__global__ __launch_bounds__(256) void topk_kernel(
    const float* __restrict__ X,      // x fp32 [TOK, DM]
    const float* __restrict__ benc)   // b_enc
{
    extern __shared__ unsigned sm[];   // DH values (64 KB)
    __shared__ int    s_red;
    __shared__ int    s_scan[256];
    __shared__ int    s_cidx[CMAX];
    __shared__ double s_cval[CMAX];

    const int row = blockIdx.x;
    const int tid = threadIdx.x;
    const int wid = tid >> 5, lane = tid & 31;
    const unsigned* z = (const unsigned*)(g_z + (long)row * DH);
    const float* xr = X + (long)row * DM;

    const uint4* z4 = (const uint4*)z;
    uint4* s4 = (uint4*)sm;
    for (int i = tid; i < DH / 4; i += 256) s4[i] = z4[i];
    __syncthreads();

    // largest t with count(v >= t) >= KSEL (uint order == float order, v >= 0)
    unsigned lo = 0u, hi = 0x7F800000u;
    while (lo < hi) {
        unsigned mid = lo + ((hi - lo + 1) >> 1);
        if (tid == 0) s_red = 0;
        __syncthreads();
        int c = 0;
#pragma unroll 8
        for (int i = 0; i < DH / 256; i++)
            c += (sm[i * 256 + tid] >= mid) ? 1 : 0;
#pragma unroll
        for (int o = 16; o; o >>= 1) c += __shfl_xor_sync(0xFFFFFFFFu, c, o);
        if ((tid & 31) == 0) atomicAdd(&s_red, c);
        __syncthreads();
        int cnt = s_red;
        if (cnt >= KSEL) lo = mid; else hi = mid - 1;
        __syncthreads();
    }
    const unsigned t = lo;
    const float tf = __uint_as_float(t);
    const int base = tid * (DH / 256);

    bool done = false;

    if (tf > 2.0f * RWIN) {
        const unsigned hib = __float_as_uint(tf + RWIN);
        const unsigned lob = __float_as_uint(tf - RWIN);

        // candidate gather: v in [lob, hib]
        int nc = 0;
#pragma unroll 8
        for (int i = 0; i < DH / 256; i++) {
            unsigned v = sm[base + i];
            nc += (v >= lob && v <= hib) ? 1 : 0;
        }
        s_scan[tid] = nc;
        __syncthreads();
        for (int off = 1; off < 256; off <<= 1) {
            int v = (tid >= off) ? s_scan[tid - off] : 0;
            __syncthreads();
            s_scan[tid] += v;
            __syncthreads();
        }
        const int cC = s_scan[255];
        if (cC <= CMAX) {
            int cw = s_scan[tid] - nc;
            for (int i = 0; i < DH / 256; i++) {
                unsigned v = sm[base + i];
                if (v >= lob && v <= hib) s_cidx[cw++] = base + i;
            }
            __syncthreads();

            // pass A: certainly-in (v > hib), ascending index
            int ng = 0;
#pragma unroll 8
            for (int i = 0; i < DH / 256; i++) ng += (sm[base + i] > hib) ? 1 : 0;
            s_scan[tid] = ng;
            __syncthreads();
            for (int off = 1; off < 256; off <<= 1) {
                int v = (tid >= off) ? s_scan[tid - off] : 0;
                __syncthreads();
                s_scan[tid] += v;
                __syncthreads();
            }
            const int cA = s_scan[255];
            int w = s_scan[tid] - ng;
            for (int i = 0; i < DH / 256; i++) {
                unsigned v = sm[base + i];
                if (v > hib) g_idx[row * KSEL + w++] = base + i;
            }
            __syncthreads();

            // exact df recompute of candidates (warp per candidate)
            for (int c = wid; c < cC; c += 8) {
                const int fi = s_cidx[c];
                double d = df_dot_warp(xr, g_WT + (long)fi * DM, lane);
                if (lane == 0) {
                    d += (double)benc[fi];
                    s_cval[c] = d > 0.0 ? d : 0.0;
                }
            }
            __syncthreads();

            // rank candidates (value desc, index asc); keep top (KSEL-cA)
            const int need = KSEL - cA;
            for (int c = tid; c < cC; c += 256) {
                const double v = s_cval[c];
                const int fi = s_cidx[c];
                int rank = 0;
                for (int c2 = 0; c2 < cC; c2++) {
                    const double u = s_cval[c2];
                    if (u > v || (u == v && s_cidx[c2] < fi)) rank++;
                }
                if (rank < need) g_idx[row * KSEL + cA + rank] = fi;
            }
            __syncthreads();

            // exact df recompute of ALL selected values
            for (int j = wid; j < KSEL; j += 8) {
                const int fi = g_idx[row * KSEL + j];
                double d = df_dot_warp(xr, g_WT + (long)fi * DM, lane);
                if (lane == 0) {
                    d += (double)benc[fi];
                    g_val[row * KSEL + j] = (float)(d > 0.0 ? d : 0.0);
                }
            }
            if (tid == 0) g_cnt[row] = KSEL;
            done = true;
        }
        __syncthreads();
    }

    if (!done) {
        // fallback: tiny threshold / overflow — bf16-level values OK here
        int ng = 0;
#pragma unroll 8
        for (int i = 0; i < DH / 256; i++) ng += (sm[base + i] > t) ? 1 : 0;
        s_scan[tid] = ng;
        __syncthreads();
        for (int off = 1; off < 256; off <<= 1) {
            int v = (tid >= off) ? s_scan[tid - off] : 0;
            __syncthreads();
            s_scan[tid] += v;
            __syncthreads();
        }
        const int c_gt = s_scan[255];
        int w = s_scan[tid] - ng;
        for (int i = 0; i < DH / 256; i++) {
            unsigned v = sm[base + i];
            if (v > t) {
                g_idx[row * KSEL + w] = base + i;
                g_val[row * KSEL + w] = __uint_as_float(v);
                w++;
            }
        }
        int cnt_final = c_gt;
        if (t != 0u) {
            __syncthreads();
            int ne = 0;
#pragma unroll 8
            for (int i = 0; i < DH / 256; i++) ne += (sm[base + i] == t) ? 1 : 0;
            s_scan[tid] = ne;
            __syncthreads();
            for (int off = 1; off < 256; off <<= 1) {
                int v = (tid >= off) ? s_scan[tid - off] : 0;
                __syncthreads();
                s_scan[tid] += v;
                __syncthreads();
            }
            int pos = c_gt + s_scan[tid] - ne;
            for (int i = 0; i < DH / 256; i++) {
                if (sm[base + i] == t) {
                    if (pos < KSEL) {
                        g_idx[row * KSEL + pos] = base + i;
                        g_val[row * KSEL + pos] = __uint_as_float(t);
                    }
                    pos++;
                }
            }
            cnt_final = KSEL;
        }
        if (tid == 0) g_cnt[row] = cnt_final;
    }
}

// ============================================================
// Decode: y[row,:] = b_dec + sum_j val_j * W_dec[idx_j, :]
// ============================================================
__global__ __launch_bounds__(256) void decode_kernel(
    const float* __restrict__ Wd,
    const float* __restrict__ bd,
    float* __restrict__ Y)
{
    __shared__ float s_val[KSEL];
    __shared__ int   s_idx[KSEL];
    const int row = blockIdx.x;
    const int tid = threadIdx.x;
    const int cnt = g_cnt[row];

    if (tid < KSEL) {
        s_idx[tid] = (tid < cnt) ? g_idx[row * KSEL + tid] : 0;
        s_val[tid] = (tid < cnt) ? g_val[row * KSEL + tid] : 0.f;
    }
    __syncthreads();

    float4 acc = ((const float4*)bd)[tid];
#pragma unroll 4
    for (int j = 0; j < cnt; j++) {
        const float v = s_val[j];
        const float4 wv = ((const float4*)(Wd + (long)s_idx[j] * DM))[tid];
        acc.x = fmaf(v, wv.x, acc.x);
        acc.y = fmaf(v, wv.y, acc.y);
        acc.z = fmaf(v, wv.z, acc.z);
        acc.w = fmaf(v, wv.w, acc.w);
    }
    ((float4*)Y)[(long)row * (DM / 4) + tid] = acc;
}

// ============================================================
extern "C" void kernel_launch(void* const* d_in, const int* in_sizes, int n_in,
                              void* d_out, int out_size)
{
    const float* x     = (const float*)d_in[0];
    const float* W_enc = (const float*)d_in[1];
    const float* b_enc = (const float*)d_in[2];
    const float* W_dec = (const float*)d_in[3];
    const float* b_dec = (const float*)d_in[4];
    float* y = (float*)d_out;

    split_x_kernel<<<(TOK * DM) / (256 * 4), 256>>>(x);
    split_w_kernel<<<dim3(DH / 32, DM / 32), dim3(32, 8)>>>(W_enc);

    cudaFuncSetAttribute(encode_mma_kernel,
                         cudaFuncAttributeMaxDynamicSharedMemorySize, SMEM_DYN);
    dim3 ge(DH / BN, TOK / BM);   // (64, 32)
    encode_mma_kernel<<<ge, 256, SMEM_DYN>>>(b_enc);

    cudaFuncSetAttribute(topk_kernel,
                         cudaFuncAttributeMaxDynamicSharedMemorySize, DH * 4);
    topk_kernel<<<TOK, 256, DH * 4>>>(x, b_enc);

    decode_kernel<<<TOK, 256>>>(W_dec, b_dec, y);
}